// round 7
// baseline (speedup 1.0000x reference)
#include <cuda_runtime.h>
#include <cstdint>

#define FFTC 256
#define NL 11
#define TT 2048
#define NCLUS 8
#define NSLOT 24
#define MEMCOLS 2047                 // sum of dilations 1+2+...+1024

// Persistent state (recomputed every kernel_launch for determinism)
__device__ float g_mem[MEMCOLS*FFTC];        // ring buffers, layer j at offset (2^j - 1)
__device__ float g_cond[NL*16*FFTC];         // cond projections per (layer, frame)
__device__ float g_emb[256*FFTC];            // tanh(emb_raw)

// ---------------- PTX helpers ----------------
__device__ __forceinline__ uint32_t smem_u32(const void* p){
  uint32_t a;
  asm("{ .reg .u64 t; cvta.to.shared.u64 t, %1; cvt.u32.u64 %0, t; }" : "=r"(a) : "l"(p));
  return a;
}
__device__ __forceinline__ uint32_t mapa32(uint32_t addr, uint32_t rank){
  uint32_t r; asm("mapa.shared::cluster.u32 %0, %1, %2;" : "=r"(r) : "r"(addr), "r"(rank));
  return r;
}
__device__ __forceinline__ void st_remote_f32(uint32_t addr, float v){
  asm volatile("st.shared::cluster.f32 [%0], %1;" :: "r"(addr), "f"(v) : "memory");
}
__device__ __forceinline__ void st_remote4(uint32_t addr, float4 v){
  asm volatile("st.shared::cluster.v4.f32 [%0], {%1,%2,%3,%4};"
               :: "r"(addr), "f"(v.x), "f"(v.y), "f"(v.z), "f"(v.w) : "memory");
}
__device__ __forceinline__ void bar_arrive_remote(uint32_t bar){
  asm volatile("mbarrier.arrive.release.cluster.shared::cluster.b64 _, [%0];"
               :: "r"(bar) : "memory");
}
__device__ __forceinline__ void bar_init(uint32_t bar, uint32_t count){
  asm volatile("mbarrier.init.shared.b64 [%0], %1;" :: "r"(bar), "r"(count) : "memory");
}
__device__ __forceinline__ void bar_wait(uint32_t bar, uint32_t parity){
  uint32_t done;
  asm volatile("{\n\t.reg .pred P;\n\t"
    "mbarrier.try_wait.parity.acquire.cluster.shared::cta.b64 P, [%1], %2;\n\t"
    "selp.b32 %0, 1, 0, P;\n\t}"
    : "=r"(done) : "r"(bar), "r"(parity) : "memory");
  while (!done){
    asm volatile("{\n\t.reg .pred P;\n\t"
      "mbarrier.try_wait.parity.acquire.cluster.shared::cta.b64 P, [%1], %2, 0x989680;\n\t"
      "selp.b32 %0, 1, 0, P;\n\t}"
      : "=r"(done) : "r"(bar), "r"(parity) : "memory");
  }
}
__device__ __forceinline__ void cluster_sync_all(){
  asm volatile("barrier.cluster.arrive.aligned;" ::: "memory");
  asm volatile("barrier.cluster.wait.aligned;"   ::: "memory");
}

struct F16v { float4 a,b,c,d; };
__device__ __forceinline__ F16v ld16(const float* p){
  const float4* q = (const float4*)p;
  F16v r; r.a=q[0]; r.b=q[1]; r.c=q[2]; r.d=q[3]; return r;
}
__device__ __forceinline__ float dot4(float4 w, float4 v, float p){
  p = fmaf(w.x,v.x,p); p = fmaf(w.y,v.y,p); p = fmaf(w.z,v.z,p); p = fmaf(w.w,v.w,p); return p;
}
__device__ __forceinline__ float dot16(const F16v& w, const F16v& v, float p){
  p = dot4(w.a,v.a,p); p = dot4(w.b,v.b,p); p = dot4(w.c,v.c,p); p = dot4(w.d,v.d,p); return p;
}
__device__ __forceinline__ float red16(float p){
  #pragma unroll
  for (int k=8;k>0;k>>=1) p += __shfl_xor_sync(0xffffffffu, p, k);
  return p;
}

// ---------------- init: zero ring buffers ----------------
__global__ void init_state(){
  size_t i = (size_t)blockIdx.x*blockDim.x + threadIdx.x;
  size_t stride = (size_t)gridDim.x*blockDim.x;
  for (size_t k=i; k<(size_t)MEMCOLS*FFTC; k+=stride) g_mem[k] = 0.0f;
}

// ---------------- precompute: emb = tanh(emb_raw); cond[j][f] = condW[j] @ y[:,f] ----------------
__global__ void precompute(const float* __restrict__ y,
                           const float* __restrict__ emb_raw,
                           const float* __restrict__ condW){
  int b = blockIdx.x, tid = threadIdx.x;
  if (b < 256) {
    g_emb[b*256 + tid] = tanhf(emb_raw[b*256 + tid]);
  } else {
    int b2 = b - 256;
    int j = b2 >> 4, f = b2 & 15;
    int row = j*256 + tid;
    float acc = 0.0f;
    #pragma unroll
    for (int c=0; c<80; c++) acc = fmaf(condW[row*80 + c], y[c*16 + f], acc);
    g_cond[(j*16 + f)*256 + tid] = acc;
  }
}

// ---------------- main persistent kernel: cluster of 8 CTAs x 512 threads ----------------
// thread t: row_l = t>>4 (32 rows/CTA), seg = t&15 (16 cols of 16 elems each)
// Per stage: seg0 pushes value to all 8 CTAs' SMEM (DSMEM), CTA bar, tid0 remote-arrives.
// Consumers wait on LOCAL mbarrier (acquire.cluster) and read x from LOCAL SMEM.
__global__ void __launch_bounds__(512,1) __cluster_dims__(NCLUS,1,1) fftnet_main(
  const float* __restrict__ WVp, const float* __restrict__ WVc,
  const float* __restrict__ Wow, const float* __restrict__ Wob,
  const float* __restrict__ endw, const float* __restrict__ endb,
  const float* __restrict__ samples, float* __restrict__ out)
{
  __shared__ __align__(16) float xbuf[NSLOT][FFTC];          // 24 KB slot ring
  __shared__ __align__(8)  unsigned long long bars[NSLOT];   // per-slot mbarrier
  const int tid = threadIdx.x;
  uint32_t rank; asm("mov.u32 %0, %%cluster_ctarank;" : "=r"(rank));
  const int row_l = tid >> 4;
  const int seg = tid & 15;
  const int r = (int)rank*32 + row_l;    // global output row owned by this thread group
  const int c0 = seg*16;                 // column chunk base

  const uint32_t xb_u  = smem_u32(&xbuf[0][0]);
  const uint32_t bar_u = smem_u32(&bars[0]);
  if (tid == 0){
    #pragma unroll
    for (int s=0;s<23;s++) bar_init(bar_u + s*8, NCLUS);  // tid0 of each CTA arrives
    bar_init(bar_u + 23*8, 32);                           // 32 sampler lanes arrive
  }
  __syncthreads();
  cluster_sync_all();   // all mbarriers initialized cluster-wide before any remote traffic

  uint32_t px[NCLUS], pbar[NCLUS];
  #pragma unroll
  for (int p=0;p<NCLUS;p++){ px[p] = mapa32(xb_u, p); pbar[p] = mapa32(bar_u, p); }

  // initial broadcast: x0 = emb[127] into slot 23 of every CTA (completion #1, parity 0)
  if (rank == 0 && tid < 32){
    const int lane = tid;
    float4 e0 = *(const float4*)(g_emb + 127*256 + lane*8);
    float4 e1 = *(const float4*)(g_emb + 127*256 + lane*8 + 4);
    #pragma unroll
    for (int p=0;p<NCLUS;p++){
      st_remote4(px[p] + 23*1024 + lane*32,      e0);
      st_remote4(px[p] + 23*1024 + lane*32 + 16, e1);
      bar_arrive_remote(pbar[p] + 23*8);   // release orders this lane's stores
    }
  }

  float xr = 0.0f;  // x_in[r], held by seg==0 threads across stage A -> B

  for (int t=0; t<TT; ++t) {
    const int f = t >> 7;
    const uint32_t parity = (uint32_t)(t & 1);

    #pragma unroll 1
    for (int j=0; j<NL; ++j) {
      const int col = ((1<<j) - 1) + (t & ((1<<j) - 1));  // ring column for layer j
      const int slot_in = (j == 0) ? 23 : (2*j - 1);
      const int slotA = 2*j, slotB = 2*j + 1;
      { // ---- stage A: h = relu(cond + Wp@mem_col + Wc@x) ----
        F16v wp = ld16(WVp + (j*FFTC + r)*FFTC + c0);
        F16v mc = ld16(g_mem + col*FFTC + c0);
        F16v wc = ld16(WVc + (j*FFTC + r)*FFTC + c0);
        float part = (seg==0) ? g_cond[(j*16 + f)*FFTC + r] : 0.0f;
        part = dot16(wp, mc, part);
        bar_wait(bar_u + slot_in*8, parity);
        const float* xb = xbuf[slot_in];
        F16v xv = ld16(xb + c0);
        if (seg==0) xr = xb[r];
        part = dot16(wc, xv, part);
        part = red16(part);
        float hval = fmaxf(part, 0.0f);
        if (seg==0){
          const uint32_t off = (uint32_t)slotA*1024 + (uint32_t)r*4;
          #pragma unroll
          for (int p=0;p<NCLUS;p++) st_remote_f32(px[p] + off, hval);
        }
        __syncthreads();    // buffer anti-dep + orders seg0 stores before tid0 arrive
        if (tid==0){
          #pragma unroll
          for (int p=0;p<NCLUS;p++) bar_arrive_remote(pbar[p] + slotA*8);
        }
      }
      { // ---- stage B: x' = relu(Wo@h + b + x); deferred ring write of x ----
        F16v wo = ld16(Wow + (j*FFTC + r)*FFTC + c0);
        float part = (seg==0) ? Wob[j*FFTC + r] : 0.0f;
        bar_wait(bar_u + slotA*8, parity);
        if (seg==0) g_mem[col*FFTC + r] = xr;  // safe: all stage-A reads done cluster-wide
        F16v hv = ld16(xbuf[slotA] + c0);
        part = dot16(wo, hv, part);
        part = red16(part);
        float xn = fmaxf(part + xr, 0.0f);     // meaningful in seg0 lanes only
        if (seg==0){
          const uint32_t off = (uint32_t)slotB*1024 + (uint32_t)r*4;
          #pragma unroll
          for (int p=0;p<NCLUS;p++) st_remote_f32(px[p] + off, xn);
        }
        __syncthreads();
        if (tid==0){
          #pragma unroll
          for (int p=0;p<NCLUS;p++) bar_arrive_remote(pbar[p] + slotB*8);
        }
      }
    }

    { // ---- logits = end_w @ x + end_b  (pushed to CTA0 only, slot 22) ----
      F16v ew = ld16(endw + r*FFTC + c0);
      float part = (seg==0) ? endb[r] : 0.0f;
      bar_wait(bar_u + 21*8, parity);
      F16v xv = ld16(xbuf[21] + c0);
      part = dot16(ew, xv, part);
      part = red16(part);
      if (seg==0) st_remote_f32(px[0] + 22*1024 + (uint32_t)r*4, part); // C_SCALE == 1
      __syncthreads();
      if (tid==0) bar_arrive_remote(pbar[0] + 22*8);
    }

    // ---- sampler (warp 0 of CTA 0): softmax -> cumsum -> first(cum > u) ----
    if (rank == 0 && tid < 32){
      const int lane = tid;
      float u = samples[t];                    // prefetch before the wait
      bar_wait(bar_u + 22*8, parity);
      const float* lb = xbuf[22];
      float4 va = *(const float4*)(lb + lane*8);
      float4 vb = *(const float4*)(lb + lane*8 + 4);
      float v[8] = {va.x,va.y,va.z,va.w,vb.x,vb.y,vb.z,vb.w};
      // warp max
      float m = v[0];
      #pragma unroll
      for (int k=1;k<8;k++) m = fmaxf(m, v[k]);
      #pragma unroll
      for (int k=16;k>0;k>>=1) m = fmaxf(m, __shfl_xor_sync(0xffffffffu, m, k));
      // exp + warp total
      float e[8]; float sl = 0.0f;
      #pragma unroll
      for (int k=0;k<8;k++){ e[k] = expf(v[k] - m); sl += e[k]; }
      float tot = sl;
      #pragma unroll
      for (int k=16;k>0;k>>=1) tot += __shfl_xor_sync(0xffffffffu, tot, k);
      // per-lane sequential cumsum of p = e/tot
      float cs[8]; float c = 0.0f;
      #pragma unroll
      for (int k=0;k<8;k++){ c += e[k] / tot; cs[k] = c; }
      // exclusive prefix of per-lane totals
      float inc = c;
      #pragma unroll
      for (int k=1;k<32;k<<=1){ float o = __shfl_up_sync(0xffffffffu, inc, k); if (lane>=k) inc += o; }
      float off = __shfl_up_sync(0xffffffffu, inc, 1);
      if (lane == 0) off = 0.0f;
      // first index with cumsum > u
      int cand = 1<<30;
      #pragma unroll
      for (int k=0;k<8;k++) if (cand == (1<<30) && (off + cs[k]) > u) cand = lane*8 + k;
      #pragma unroll
      for (int k=16;k>0;k>>=1) cand = min(cand, __shfl_xor_sync(0xffffffffu, cand, k));
      int sel = (cand >= 256) ? 0 : cand;
      if (lane == 0) out[t] = (float)sel;
      // broadcast emb[sel] into slot 23 of every CTA for next step
      float4 e0 = *(const float4*)(g_emb + sel*256 + lane*8);
      float4 e1 = *(const float4*)(g_emb + sel*256 + lane*8 + 4);
      #pragma unroll
      for (int p=0;p<NCLUS;p++){
        st_remote4(px[p] + 23*1024 + lane*32,      e0);
        st_remote4(px[p] + 23*1024 + lane*32 + 16, e1);
        bar_arrive_remote(pbar[p] + 23*8);
      }
    }
  }

  // Terminal cluster sync: no CTA may exit while CTA0's sampler (step TT-1) still has
  // in-flight DSMEM stores / remote mbarrier arrives targeting peer SMEM. The arrive
  // (release) / wait (acquire) pair also orders those final stores before any exit.
  cluster_sync_all();
}

extern "C" void kernel_launch(void* const* d_in, const int* in_sizes, int n_in,
                              void* d_out, int out_size) {
  // ---- Robust input binding: identify tensors by element count, not position.
  int i1280=-1, i2048=-1, i225280=-1, i2816=-1, i256=-1;
  int i65536[2] = {-1,-1}; int n65536 = 0;
  int i720[3] = {-1,-1,-1}; int n720 = 0;
  for (int i=0;i<n_in;i++){
    switch (in_sizes[i]){
      case 1280:   i1280 = i; break;
      case 2048:   i2048 = i; break;
      case 225280: i225280 = i; break;
      case 2816:   i2816 = i; break;
      case 256:    i256 = i; break;
      case 65536:  if (n65536 < 2) i65536[n65536++] = i; break;
      case 720896: if (n720 < 3) i720[n720++] = i; break;
      default: break;
    }
  }
  if (i1280<0 || i2048<0 || i225280<0 || i2816<0 || i256<0 || n65536!=2 || n720!=3){
    i1280=0; i2048=1; i65536[0]=2; i225280=3; i720[0]=4; i720[1]=5; i720[2]=6;
    i2816=7; i65536[1]=8; i256=9;
  }
  const float* y        = (const float*)d_in[i1280];     // [80,16]
  const float* samples  = (const float*)d_in[i2048];     // [2048]
  const float* condW    = (const float*)d_in[i225280];   // [2816,80]
  const float* Wob      = (const float*)d_in[i2816];     // [11,256]
  const float* endb     = (const float*)d_in[i256];      // [256]
  const float* emb_raw  = (const float*)d_in[i65536[0]]; // [256,256]
  const float* endw     = (const float*)d_in[i65536[1]]; // [256,256]
  int before = 0;
  for (int k=0;k<3;k++) if (i720[k] < i2816) before++;
  const float *WVp, *WVc, *Wow;
  if (before == 0) { Wow = (const float*)d_in[i720[0]];
                     WVp = (const float*)d_in[i720[1]];
                     WVc = (const float*)d_in[i720[2]]; }
  else             { WVp = (const float*)d_in[i720[0]];
                     WVc = (const float*)d_in[i720[1]];
                     Wow = (const float*)d_in[i720[2]]; }
  float* out = (float*)d_out;                            // [2048] sampled ids (as float32)

  init_state<<<256,256>>>();
  precompute<<<256 + NL*16, 256>>>(y, emb_raw, condW);
  fftnet_main<<<NCLUS,512>>>(WVp, WVc, Wow, Wob, endw, endb, samples, out);
}

// round 8
// speedup vs baseline: 1.8029x; 1.8029x over previous
#include <cuda_runtime.h>
#include <cstdint>

#define FFTC 256
#define NL 11
#define TT 2048
#define NCTA 8
#define SPS 13                       // flags/step: s=0 x0; s=1..11 layer partials; s=12 logits partials
#define NFLAGS ((TT+1)*SPS)
#define FSTRIDE 32                   // one 128B L2 line per flag
#define MEMCOLS 2047                 // sum of dilations 1+2+...+1024

// Persistent state (recomputed every kernel_launch for determinism)
__device__ float g_ring[(size_t)NCTA*MEMCOLS*FFTC]; // PRIVATE ring buffer per CTA
__device__ float g_cond[NL*16*FFTC];                // cond projections per (layer, frame)
__device__ float g_emb[256*FFTC];                   // tanh(emb_raw)
__device__ float g_part[12*NCTA*FFTC];              // per-layer (+logits) partial z vectors
__device__ __align__(16) float g_x0[FFTC];          // sampled embedding broadcast
__device__ unsigned g_flags[(size_t)NFLAGS*FSTRIDE];

__device__ __forceinline__ void poll_flag(int s, unsigned expect){
  const unsigned* p = g_flags + (size_t)s*FSTRIDE;
  unsigned v;
  do {
    asm volatile("ld.acquire.gpu.global.u32 %0, [%1];" : "=r"(v) : "l"(p) : "memory");
  } while (v < expect);
}
// per-warp wait: only lane 0 polls, rest of warp waits at syncwarp
__device__ __forceinline__ void wait_flag(int s, unsigned expect){
  if ((threadIdx.x & 31) == 0) poll_flag(s, expect);
  __syncwarp();
}
__device__ __forceinline__ void release_flag(int s){
  asm volatile("red.release.gpu.global.add.u32 [%0], %1;"
               :: "l"(g_flags + (size_t)s*FSTRIDE), "r"(1u) : "memory");
}
// CTA-wide signal: bar then one release-atomic (CG grid-sync pattern)
__device__ __forceinline__ void signal_flag(int s){
  __syncthreads();
  if (threadIdx.x == 0) release_flag(s);
}

struct F16v { float4 a,b,c,d; };
__device__ __forceinline__ F16v ld16(const float* p){
  const float4* q = (const float4*)p;
  F16v r; r.a=q[0]; r.b=q[1]; r.c=q[2]; r.d=q[3]; return r;
}
__device__ __forceinline__ float dot4(float4 w, float4 v, float p){
  p = fmaf(w.x,v.x,p); p = fmaf(w.y,v.y,p); p = fmaf(w.z,v.z,p); p = fmaf(w.w,v.w,p); return p;
}
__device__ __forceinline__ float dot16(const F16v& w, const F16v& v, float p){
  p = dot4(w.a,v.a,p); p = dot4(w.b,v.b,p); p = dot4(w.c,v.c,p); p = dot4(w.d,v.d,p); return p;
}
__device__ __forceinline__ float red16(float p){
  #pragma unroll
  for (int k=8;k>0;k>>=1) p += __shfl_xor_sync(0xffffffffu, p, k);
  return p;
}

// ---------------- init: zero mutable state ----------------
__global__ void init_state(){
  size_t i = (size_t)blockIdx.x*blockDim.x + threadIdx.x;
  size_t stride = (size_t)gridDim.x*blockDim.x;
  for (size_t k=i; k<(size_t)NCTA*MEMCOLS*FFTC; k+=stride) g_ring[k] = 0.0f;
  for (size_t k=i; k<(size_t)NFLAGS*FSTRIDE; k+=stride) g_flags[k] = 0u;
}

// ---------------- precompute: emb = tanh(emb_raw); cond[j][f] = condW[j] @ y[:,f] ----------------
__global__ void precompute(const float* __restrict__ y,
                           const float* __restrict__ emb_raw,
                           const float* __restrict__ condW){
  int b = blockIdx.x, tid = threadIdx.x;
  if (b < 256) {
    g_emb[b*256 + tid] = tanhf(emb_raw[b*256 + tid]);
  } else {
    int b2 = b - 256;
    int j = b2 >> 4, f = b2 & 15;
    int row = j*256 + tid;
    float acc = 0.0f;
    #pragma unroll
    for (int c=0; c<80; c++) acc = fmaf(condW[row*80 + c], y[c*16 + f], acc);
    g_cond[(j*16 + f)*256 + tid] = acc;
  }
}

// ---------------- main persistent kernel: 8 CTAs x 512 threads, gmem-flag fabric ----------------
// Stage-A mapping: row_l = tid>>4 (32 h-rows/CTA), seg = tid&15 (16-col chunks).
// Partial-z mapping: zrow = tid>>1 (256 outputs), half = tid&1 (two 16-wide inner halves).
// One chip-wide sync per layer (partial-z publish); x' computed redundantly in every CTA.
__global__ void __launch_bounds__(512,1) fftnet_main(
  const float* __restrict__ WVp, const float* __restrict__ WVc,
  const float* __restrict__ Wow, const float* __restrict__ Wob,
  const float* __restrict__ endw, const float* __restrict__ endb,
  const float* __restrict__ samples, float* __restrict__ out)
{
  __shared__ __align__(16) float xs[FFTC];   // current x, full vector (identical in all CTAs)
  __shared__ __align__(16) float hs[32];     // this CTA's h rows
  __shared__ __align__(16) float lg[FFTC];   // CTA0: logits
  const int tid = threadIdx.x;
  const int blk = blockIdx.x;
  const int row_l = tid >> 4;
  const int seg = tid & 15;
  const int r = blk*32 + row_l;
  const int c0 = seg*16;
  const int zrow = tid >> 1;
  const int half = tid & 1;
  const int hoff = half*16;
  float* ring = g_ring + (size_t)blk*MEMCOLS*FFTC;

  // seed x0 = emb[127], release flag (t=0, s=0)
  if (blk == 0 && tid < 32){
    const int lane = tid;
    float4 e0 = *(const float4*)(g_emb + 127*256 + lane*8);
    float4 e1 = *(const float4*)(g_emb + 127*256 + lane*8 + 4);
    *(float4*)(g_x0 + lane*8)     = e0;
    *(float4*)(g_x0 + lane*8 + 4) = e1;
    __syncwarp();
    if (lane == 0) release_flag(0);
  }

  for (int t=0; t<TT; ++t){
    const int f = t >> 7;
    const int base = t*SPS;

    #pragma unroll 1
    for (int j=0; j<NL; ++j){
      const int col = ((1<<j) - 1) + (t & ((1<<j) - 1));
      // ---- prefetch everything independent of this layer's input x ----
      F16v wp = ld16(WVp + (j*FFTC + r)*FFTC + c0);
      F16v mc = ld16(ring + col*FFTC + c0);
      float part = (seg==0) ? g_cond[(j*16 + f)*FFTC + r] : 0.0f;
      part = dot16(wp, mc, part);                 // past-tap dot: before the wait
      F16v wc = ld16(WVc + (j*FFTC + r)*FFTC + c0);
      F16v wo = ld16(Wow + (j*FFTC + zrow)*FFTC + blk*32 + hoff);
      float wobp = (j>0 && tid<FFTC) ? Wob[(j-1)*FFTC + tid] : 0.0f;

      if (j == 0){
        wait_flag(base + 0, 1u);                  // x0 from sampler
        F16v xv = ld16(g_x0 + c0);
        if (tid < FFTC) xs[tid] = g_x0[tid];
        part = dot16(wc, xv, part);
      } else {
        wait_flag(base + j, NCTA);                // partials of layer j-1
        if (tid < FFTC){
          float s1 = wobp;
          #pragma unroll
          for (int k=0;k<NCTA;k++) s1 += g_part[((j-1)*NCTA + k)*FFTC + tid];
          xs[tid] = fmaxf(s1 + xs[tid], 0.0f);    // x' = relu(z + b + x)
        }
        __syncthreads();
        F16v xv = ld16(xs + c0);
        part = dot16(wc, xv, part);
      }
      part = red16(part);
      if (seg==0) hs[row_l] = fmaxf(part, 0.0f);
      __syncthreads();
      if (tid < FFTC) ring[col*FFTC + tid] = xs[tid];  // private ring write (off crit path)
      // partial z over this CTA's 32 h rows
      F16v hv = ld16(hs + hoff);
      float pk = dot16(wo, hv, 0.0f);
      float oth = __shfl_xor_sync(0xffffffffu, pk, 1);
      float z = (half==0) ? (pk + oth) : (oth + pk);
      if (half==0) g_part[(j*NCTA + blk)*FFTC + zrow] = z;
      signal_flag(base + 1 + j);
    }

    { // ---- logits: x' after layer 10, then partial endw slice ----
      F16v ew = ld16(endw + zrow*FFTC + blk*32 + hoff);
      float wobL = (tid<FFTC) ? Wob[10*FFTC + tid] : 0.0f;
      wait_flag(base + 11, NCTA);                 // partials of layer 10
      if (tid < FFTC){
        float s1 = wobL;
        #pragma unroll
        for (int k=0;k<NCTA;k++) s1 += g_part[(10*NCTA + k)*FFTC + tid];
        xs[tid] = fmaxf(s1 + xs[tid], 0.0f);
      }
      __syncthreads();
      F16v xv = ld16(xs + blk*32 + hoff);
      float pk = dot16(ew, xv, 0.0f);
      float oth = __shfl_xor_sync(0xffffffffu, pk, 1);
      float z = (half==0) ? (pk + oth) : (oth + pk);
      if (half==0) g_part[(11*NCTA + blk)*FFTC + zrow] = z;
      signal_flag(base + 12);
    }

    // ---- CTA0 only: assemble logits, sample, broadcast x0 for t+1 ----
    if (blk == 0){
      float u = (tid < 32) ? samples[t] : 0.0f;
      wait_flag(base + 12, NCTA);
      if (tid < FFTC){
        float s1 = endb[tid];
        #pragma unroll
        for (int k=0;k<NCTA;k++) s1 += g_part[(11*NCTA + k)*FFTC + tid];
        lg[tid] = s1;                             // C_SCALE == 1
      }
      __syncthreads();
      if (tid < 32){
        const int lane = tid;
        float4 va = *(const float4*)(lg + lane*8);
        float4 vb = *(const float4*)(lg + lane*8 + 4);
        float v[8] = {va.x,va.y,va.z,va.w,vb.x,vb.y,vb.z,vb.w};
        float m = v[0];
        #pragma unroll
        for (int k=1;k<8;k++) m = fmaxf(m, v[k]);
        #pragma unroll
        for (int k=16;k>0;k>>=1) m = fmaxf(m, __shfl_xor_sync(0xffffffffu, m, k));
        float e[8]; float sl = 0.0f;
        #pragma unroll
        for (int k=0;k<8;k++){ e[k] = expf(v[k] - m); sl += e[k]; }
        float tot = sl;
        #pragma unroll
        for (int k=16;k>0;k>>=1) tot += __shfl_xor_sync(0xffffffffu, tot, k);
        float cs[8]; float c = 0.0f;
        #pragma unroll
        for (int k=0;k<8;k++){ c += e[k] / tot; cs[k] = c; }
        float inc = c;
        #pragma unroll
        for (int k=1;k<32;k<<=1){ float o = __shfl_up_sync(0xffffffffu, inc, k); if (lane>=k) inc += o; }
        float off = __shfl_up_sync(0xffffffffu, inc, 1);
        if (lane == 0) off = 0.0f;
        int cand = 1<<30;
        #pragma unroll
        for (int k=0;k<8;k++) if (cand == (1<<30) && (off + cs[k]) > u) cand = lane*8 + k;
        #pragma unroll
        for (int k=16;k>0;k>>=1) cand = min(cand, __shfl_xor_sync(0xffffffffu, cand, k));
        int sel = (cand >= 256) ? 0 : cand;
        if (lane == 0) out[t] = (float)sel;
        float4 e0 = *(const float4*)(g_emb + sel*256 + lane*8);
        float4 e1 = *(const float4*)(g_emb + sel*256 + lane*8 + 4);
        *(float4*)(g_x0 + lane*8)     = e0;
        *(float4*)(g_x0 + lane*8 + 4) = e1;
        __syncwarp();
        if (lane == 0) release_flag((t+1)*SPS + 0);
      }
    }
  }
}

extern "C" void kernel_launch(void* const* d_in, const int* in_sizes, int n_in,
                              void* d_out, int out_size) {
  // ---- Robust input binding: identify tensors by element count, not position.
  int i1280=-1, i2048=-1, i225280=-1, i2816=-1, i256=-1;
  int i65536[2] = {-1,-1}; int n65536 = 0;
  int i720[3] = {-1,-1,-1}; int n720 = 0;
  for (int i=0;i<n_in;i++){
    switch (in_sizes[i]){
      case 1280:   i1280 = i; break;
      case 2048:   i2048 = i; break;
      case 225280: i225280 = i; break;
      case 2816:   i2816 = i; break;
      case 256:    i256 = i; break;
      case 65536:  if (n65536 < 2) i65536[n65536++] = i; break;
      case 720896: if (n720 < 3) i720[n720++] = i; break;
      default: break;
    }
  }
  if (i1280<0 || i2048<0 || i225280<0 || i2816<0 || i256<0 || n65536!=2 || n720!=3){
    i1280=0; i2048=1; i65536[0]=2; i225280=3; i720[0]=4; i720[1]=5; i720[2]=6;
    i2816=7; i65536[1]=8; i256=9;
  }
  const float* y        = (const float*)d_in[i1280];     // [80,16]
  const float* samples  = (const float*)d_in[i2048];     // [2048]
  const float* condW    = (const float*)d_in[i225280];   // [2816,80]
  const float* Wob      = (const float*)d_in[i2816];     // [11,256]
  const float* endb     = (const float*)d_in[i256];      // [256]
  const float* emb_raw  = (const float*)d_in[i65536[0]]; // [256,256]
  const float* endw     = (const float*)d_in[i65536[1]]; // [256,256]
  int before = 0;
  for (int k=0;k<3;k++) if (i720[k] < i2816) before++;
  const float *WVp, *WVc, *Wow;
  if (before == 0) { Wow = (const float*)d_in[i720[0]];
                     WVp = (const float*)d_in[i720[1]];
                     WVc = (const float*)d_in[i720[2]]; }
  else             { WVp = (const float*)d_in[i720[0]];
                     WVc = (const float*)d_in[i720[1]];
                     Wow = (const float*)d_in[i720[2]]; }
  float* out = (float*)d_out;                            // [2048] sampled ids (as float32)

  init_state<<<256,256>>>();
  precompute<<<256 + NL*16, 256>>>(y, emb_raw, condW);
  fftnet_main<<<NCTA,512>>>(WVp, WVc, Wow, Wob, endw, endb, samples, out);
}

// round 9
// speedup vs baseline: 1.8181x; 1.0084x over previous
#include <cuda_runtime.h>
#include <cstdint>

#define FFTC 256
#define NL 11
#define TT 2048
#define NCTA 8
#define SPS 12                       // flags/step: s=0..10 layer-partial publishes; s=11 logits partials
#define NFLAGS (TT*SPS)
#define FSTRIDE 32                   // one 128B L2 line per flag
#define MEMCOLS 2047                 // sum of dilations 1+2+...+1024

// Persistent state (recomputed every kernel_launch for determinism)
__device__ float g_ring[(size_t)NCTA*MEMCOLS*FFTC]; // PRIVATE ring buffer per CTA
__device__ float g_cond[NL*16*FFTC];                // cond projections per (layer, frame)
__device__ float g_emb[256*FFTC];                   // tanh(emb_raw)
__device__ float g_part[12*NCTA*FFTC];              // per-layer (+logits) partial z vectors
__device__ unsigned g_flags[(size_t)NFLAGS*FSTRIDE];

__device__ __forceinline__ void poll_flag(int s, unsigned expect){
  const unsigned* p = g_flags + (size_t)s*FSTRIDE;
  unsigned v;
  do {
    asm volatile("ld.acquire.gpu.global.u32 %0, [%1];" : "=r"(v) : "l"(p) : "memory");
  } while (v < expect);
}
__device__ __forceinline__ void release_flag(int s){
  asm volatile("red.release.gpu.global.add.u32 [%0], %1;"
               :: "l"(g_flags + (size_t)s*FSTRIDE), "r"(1u) : "memory");
}

struct F16v { float4 a,b,c,d; };
__device__ __forceinline__ F16v ld16(const float* p){
  const float4* q = (const float4*)p;
  F16v r; r.a=q[0]; r.b=q[1]; r.c=q[2]; r.d=q[3]; return r;
}
__device__ __forceinline__ float dot4(float4 w, float4 v, float p){
  p = fmaf(w.x,v.x,p); p = fmaf(w.y,v.y,p); p = fmaf(w.z,v.z,p); p = fmaf(w.w,v.w,p); return p;
}
__device__ __forceinline__ float dot16(const F16v& w, const F16v& v, float p){
  p = dot4(w.a,v.a,p); p = dot4(w.b,v.b,p); p = dot4(w.c,v.c,p); p = dot4(w.d,v.d,p); return p;
}
__device__ __forceinline__ float red16(float p){
  #pragma unroll
  for (int k=8;k>0;k>>=1) p += __shfl_xor_sync(0xffffffffu, p, k);
  return p;
}

// ---------------- init + precompute fused (also re-phases ncu onto fftnet_main) ----------------
__global__ void init_all(const float* __restrict__ y,
                         const float* __restrict__ emb_raw,
                         const float* __restrict__ condW){
  const int b = blockIdx.x, tid = threadIdx.x;
  if (b < 256) {
    g_emb[b*256 + tid] = tanhf(emb_raw[b*256 + tid]);
  } else if (b < 256 + NL*16) {
    int b2 = b - 256;
    int j = b2 >> 4, f = b2 & 15;
    int row = j*256 + tid;
    float acc = 0.0f;
    #pragma unroll
    for (int c=0; c<80; c++) acc = fmaf(condW[row*80 + c], y[c*16 + f], acc);
    g_cond[(j*16 + f)*256 + tid] = acc;
  }
  size_t i = (size_t)b*blockDim.x + tid;
  size_t stride = (size_t)gridDim.x*blockDim.x;
  for (size_t k=i; k<(size_t)NCTA*MEMCOLS*FFTC; k+=stride) g_ring[k] = 0.0f;
  for (size_t k=i; k<(size_t)NFLAGS*FSTRIDE; k+=stride) g_flags[k] = 0u;
}

// ---------------- main persistent kernel: 8 CTAs x 512 threads, gmem-flag fabric ----------------
// Stage-A mapping: row_l = tid>>4 (32 h-rows/CTA), seg = tid&15 (16-col chunks).
// Partial-z mapping: zrow = tid>>1 (256 outputs), half = tid&1 (two 16-wide inner halves).
// One chip-wide sync per layer; x', logits assembly, and the SAMPLER are computed
// redundantly in every CTA (deterministic), so no x0-broadcast sync exists.
// Waits use a single poller (tid0) + CTA barrier to kill poll-wakeup jitter.
__global__ void __launch_bounds__(512,1) fftnet_main(
  const float* __restrict__ WVp, const float* __restrict__ WVc,
  const float* __restrict__ Wow, const float* __restrict__ Wob,
  const float* __restrict__ endw, const float* __restrict__ endb,
  const float* __restrict__ samples, float* __restrict__ out)
{
  __shared__ __align__(16) float xs[FFTC];   // current x (identical in all CTAs)
  __shared__ __align__(16) float hs[32];     // this CTA's h rows
  __shared__ __align__(16) float lg[FFTC];   // logits (all CTAs)
  __shared__ int s_sel;
  const int tid = threadIdx.x;
  const int blk = blockIdx.x;
  const int row_l = tid >> 4;
  const int seg = tid & 15;
  const int r = blk*32 + row_l;
  const int c0 = seg*16;
  const int zrow = tid >> 1;
  const int half = tid & 1;
  const int hoff = half*16;
  float* ring = g_ring + (size_t)blk*MEMCOLS*FFTC;

  // seed x0 = emb[127] locally in every CTA (no sync needed)
  if (tid < FFTC) xs[tid] = g_emb[127*FFTC + tid];
  __syncthreads();

  for (int t=0; t<TT; ++t){
    const int f = t >> 7;
    const int base = t*SPS;

    #pragma unroll 1
    for (int j=0; j<NL; ++j){
      const int col = ((1<<j) - 1) + (t & ((1<<j) - 1));
      // ---- prefetch everything independent of this layer's input x ----
      F16v wp = ld16(WVp + (j*FFTC + r)*FFTC + c0);
      F16v mc = ld16(ring + col*FFTC + c0);
      float part = (seg==0) ? g_cond[(j*16 + f)*FFTC + r] : 0.0f;
      part = dot16(wp, mc, part);                 // past-tap dot: before the wait
      F16v wc = ld16(WVc + (j*FFTC + r)*FFTC + c0);
      F16v wo = ld16(Wow + (j*FFTC + zrow)*FFTC + blk*32 + hoff);

      if (j > 0){
        float wobp = (tid<FFTC) ? Wob[(j-1)*FFTC + tid] : 0.0f;
        if (tid==0) poll_flag(base + (j-1), NCTA);  // single poller
        __syncthreads();                            // releases all 16 warps together
        if (tid < FFTC){
          float s1 = wobp;
          #pragma unroll
          for (int k=0;k<NCTA;k++) s1 += g_part[((j-1)*NCTA + k)*FFTC + tid];
          xs[tid] = fmaxf(s1 + xs[tid], 0.0f);      // x' = relu(z + b + x)
        }
        __syncthreads();
      }
      F16v xv = ld16(xs + c0);
      part = dot16(wc, xv, part);
      part = red16(part);
      if (seg==0) hs[row_l] = fmaxf(part, 0.0f);
      __syncthreads();
      // partial z over this CTA's 32 h rows
      F16v hv = ld16(hs + hoff);
      float pk = dot16(wo, hv, 0.0f);
      float oth = __shfl_xor_sync(0xffffffffu, pk, 1);
      float z = (half==0) ? (pk + oth) : (oth + pk);
      if (half==0) g_part[(j*NCTA + blk)*FFTC + zrow] = z;
      __syncthreads();                              // all partial stores before release
      if (tid==0) release_flag(base + j);
      if (tid < FFTC) ring[col*FFTC + tid] = xs[tid];  // private, outside release drain
    }

    { // ---- logits: x' after layer 10, then partial endw slice ----
      F16v ew = ld16(endw + zrow*FFTC + blk*32 + hoff);
      float wobL = (tid<FFTC) ? Wob[10*FFTC + tid] : 0.0f;
      if (tid==0) poll_flag(base + 10, NCTA);
      __syncthreads();
      if (tid < FFTC){
        float s1 = wobL;
        #pragma unroll
        for (int k=0;k<NCTA;k++) s1 += g_part[(10*NCTA + k)*FFTC + tid];
        xs[tid] = fmaxf(s1 + xs[tid], 0.0f);
      }
      __syncthreads();
      F16v xv = ld16(xs + blk*32 + hoff);
      float pk = dot16(ew, xv, 0.0f);
      float oth = __shfl_xor_sync(0xffffffffu, pk, 1);
      float z = (half==0) ? (pk + oth) : (oth + pk);
      if (half==0) g_part[(11*NCTA + blk)*FFTC + zrow] = z;
      __syncthreads();
      if (tid==0) release_flag(base + 11);
    }

    { // ---- sampler: ALL CTAs redundantly (deterministic); no broadcast sync ----
      float u = (tid < 32) ? samples[t] : 0.0f;     // prefetch before the wait
      if (tid==0) poll_flag(base + 11, NCTA);
      __syncthreads();
      if (tid < FFTC){
        float s1 = endb[tid];
        #pragma unroll
        for (int k=0;k<NCTA;k++) s1 += g_part[(11*NCTA + k)*FFTC + tid];
        lg[tid] = s1;                               // C_SCALE == 1
      }
      __syncthreads();
      if (tid < 32){
        const int lane = tid;
        float4 va = *(const float4*)(lg + lane*8);
        float4 vb = *(const float4*)(lg + lane*8 + 4);
        float v[8] = {va.x,va.y,va.z,va.w,vb.x,vb.y,vb.z,vb.w};
        float m = v[0];
        #pragma unroll
        for (int k=1;k<8;k++) m = fmaxf(m, v[k]);
        #pragma unroll
        for (int k=16;k>0;k>>=1) m = fmaxf(m, __shfl_xor_sync(0xffffffffu, m, k));
        float e[8]; float sl = 0.0f;
        #pragma unroll
        for (int k=0;k<8;k++){ e[k] = expf(v[k] - m); sl += e[k]; }
        float tot = sl;
        #pragma unroll
        for (int k=16;k>0;k>>=1) tot += __shfl_xor_sync(0xffffffffu, tot, k);
        float cs[8]; float c = 0.0f;
        #pragma unroll
        for (int k=0;k<8;k++){ c += e[k] / tot; cs[k] = c; }
        float inc = c;
        #pragma unroll
        for (int k=1;k<32;k<<=1){ float o = __shfl_up_sync(0xffffffffu, inc, k); if (lane>=k) inc += o; }
        float off = __shfl_up_sync(0xffffffffu, inc, 1);
        if (lane == 0) off = 0.0f;
        int cand = 1<<30;
        #pragma unroll
        for (int k=0;k<8;k++) if (cand == (1<<30) && (off + cs[k]) > u) cand = lane*8 + k;
        #pragma unroll
        for (int k=16;k>0;k>>=1) cand = min(cand, __shfl_xor_sync(0xffffffffu, cand, k));
        int sel = (cand >= 256) ? 0 : cand;
        if (lane == 0){
          s_sel = sel;
          if (blk == 0) out[t] = (float)sel;
        }
      }
      __syncthreads();
      if (tid < FFTC) xs[tid] = g_emb[s_sel*FFTC + tid];  // next step's x0, locally
      __syncthreads();
    }
  }
}

extern "C" void kernel_launch(void* const* d_in, const int* in_sizes, int n_in,
                              void* d_out, int out_size) {
  // ---- Robust input binding: identify tensors by element count, not position.
  int i1280=-1, i2048=-1, i225280=-1, i2816=-1, i256=-1;
  int i65536[2] = {-1,-1}; int n65536 = 0;
  int i720[3] = {-1,-1,-1}; int n720 = 0;
  for (int i=0;i<n_in;i++){
    switch (in_sizes[i]){
      case 1280:   i1280 = i; break;
      case 2048:   i2048 = i; break;
      case 225280: i225280 = i; break;
      case 2816:   i2816 = i; break;
      case 256:    i256 = i; break;
      case 65536:  if (n65536 < 2) i65536[n65536++] = i; break;
      case 720896: if (n720 < 3) i720[n720++] = i; break;
      default: break;
    }
  }
  if (i1280<0 || i2048<0 || i225280<0 || i2816<0 || i256<0 || n65536!=2 || n720!=3){
    i1280=0; i2048=1; i65536[0]=2; i225280=3; i720[0]=4; i720[1]=5; i720[2]=6;
    i2816=7; i65536[1]=8; i256=9;
  }
  const float* y        = (const float*)d_in[i1280];     // [80,16]
  const float* samples  = (const float*)d_in[i2048];     // [2048]
  const float* condW    = (const float*)d_in[i225280];   // [2816,80]
  const float* Wob      = (const float*)d_in[i2816];     // [11,256]
  const float* endb     = (const float*)d_in[i256];      // [256]
  const float* emb_raw  = (const float*)d_in[i65536[0]]; // [256,256]
  const float* endw     = (const float*)d_in[i65536[1]]; // [256,256]
  int before = 0;
  for (int k=0;k<3;k++) if (i720[k] < i2816) before++;
  const float *WVp, *WVc, *Wow;
  if (before == 0) { Wow = (const float*)d_in[i720[0]];
                     WVp = (const float*)d_in[i720[1]];
                     WVc = (const float*)d_in[i720[2]]; }
  else             { WVp = (const float*)d_in[i720[0]];
                     WVc = (const float*)d_in[i720[1]];
                     Wow = (const float*)d_in[i720[2]]; }
  float* out = (float*)d_out;                            // [2048] sampled ids (as float32)

  init_all<<<2048,256>>>(y, emb_raw, condW);
  fftnet_main<<<NCTA,512>>>(WVp, WVc, Wow, Wob, endw, endb, samples, out);
}

// round 11
// speedup vs baseline: 2.9749x; 1.6363x over previous
#include <cuda_runtime.h>
#include <cstdint>

#define FFTC 256
#define NL 11
#define TT 2048
#define NCTA 16
#define SPS 12                       // flags/step: s=0..10 layer-partial publishes; s=11 logits partials
#define NFLAGS (TT*SPS)
#define FSTRIDE 32                   // one 128B L2 line per flag
#define MEMCOLS 2047                 // sum of dilations 1+2+...+1024

// Persistent state (recomputed every kernel_launch for determinism)
__device__ float g_ring[(size_t)NCTA*MEMCOLS*FFTC]; // PRIVATE ring buffer per CTA
__device__ float g_cond[NL*16*FFTC];                // cond projections per (layer, frame)
__device__ float g_emb[256*FFTC];                   // tanh(emb_raw)
__device__ float g_part[12*NCTA*FFTC];              // per-layer (+logits) partial z vectors
__device__ unsigned g_flags[(size_t)NFLAGS*FSTRIDE];

__device__ __forceinline__ void poll_flag(int s, unsigned expect){
  const unsigned* p = g_flags + (size_t)s*FSTRIDE;
  unsigned v;
  do {
    asm volatile("ld.acquire.gpu.global.u32 %0, [%1];" : "=r"(v) : "l"(p) : "memory");
  } while (v < expect);
}
__device__ __forceinline__ void release_flag(int s){
  asm volatile("red.release.gpu.global.add.u32 [%0], %1;"
               :: "l"(g_flags + (size_t)s*FSTRIDE), "r"(1u) : "memory");
}

// 8-float (32B) weight load: read-only, keep resident in L2 (evict_last).
// ptxas requires .v4.b64 (or .v8.b32) with L2::evict_last on sm_103a.
struct F8 { float f[8]; };
__device__ __forceinline__ F8 ldnc8(const float* p){
  unsigned long long a,b,c,d;
  asm volatile("ld.global.nc.L2::evict_last.v4.b64 {%0,%1,%2,%3}, [%4];"
               : "=l"(a), "=l"(b), "=l"(c), "=l"(d) : "l"(p));
  F8 r;
  r.f[0] = __uint_as_float((unsigned)(a));        r.f[1] = __uint_as_float((unsigned)(a>>32));
  r.f[2] = __uint_as_float((unsigned)(b));        r.f[3] = __uint_as_float((unsigned)(b>>32));
  r.f[4] = __uint_as_float((unsigned)(c));        r.f[5] = __uint_as_float((unsigned)(c>>32));
  r.f[6] = __uint_as_float((unsigned)(d));        r.f[7] = __uint_as_float((unsigned)(d>>32));
  return r;
}
// cross-CTA data: bypass L1 (L2 is the coherence point for gpu-scope flags)
__device__ __forceinline__ float ldcg(const float* p){
  float v;
  asm volatile("ld.global.cg.f32 %0, [%1];" : "=f"(v) : "l"(p));
  return v;
}

__device__ __forceinline__ float dot8(const F8& w, const float* v, float p){
  #pragma unroll
  for (int k=0;k<8;k++) p = fmaf(w.f[k], v[k], p);
  return p;
}
__device__ __forceinline__ float red32(float p){
  #pragma unroll
  for (int k=16;k>0;k>>=1) p += __shfl_xor_sync(0xffffffffu, p, k);
  return p;
}

// ---------------- init + precompute fused ----------------
__global__ void init_all(const float* __restrict__ y,
                         const float* __restrict__ emb_raw,
                         const float* __restrict__ condW){
  const int b = blockIdx.x, tid = threadIdx.x;
  if (b < 256) {
    g_emb[b*256 + tid] = tanhf(emb_raw[b*256 + tid]);
  } else if (b < 256 + NL*16) {
    int b2 = b - 256;
    int j = b2 >> 4, f = b2 & 15;
    int row = j*256 + tid;
    float acc = 0.0f;
    #pragma unroll
    for (int c=0; c<80; c++) acc = fmaf(condW[row*80 + c], y[c*16 + f], acc);
    g_cond[(j*16 + f)*256 + tid] = acc;
  }
  size_t i = (size_t)b*blockDim.x + tid;
  size_t stride = (size_t)gridDim.x*blockDim.x;
  for (size_t k=i; k<(size_t)NCTA*MEMCOLS*FFTC; k+=stride) g_ring[k] = 0.0f;
  for (size_t k=i; k<(size_t)NFLAGS*FSTRIDE; k+=stride) g_flags[k] = 0u;
}

// ---------------- main persistent kernel: 16 CTAs x 512 threads ----------------
// Stage A: warp-per-h-row (16 warps = 16 rows/CTA), 8 floats/lane, full-warp reduce.
// Partial z: zrow = tid>>1 (256 outputs), half = tid&1; 16-wide inner slice per CTA.
// One chip-wide sync per layer; x', logits and SAMPLER computed redundantly per CTA.
__global__ void __launch_bounds__(512,1) fftnet_main(
  const float* __restrict__ WVp, const float* __restrict__ WVc,
  const float* __restrict__ Wow, const float* __restrict__ Wob,
  const float* __restrict__ endw, const float* __restrict__ endb,
  const float* __restrict__ samples, float* __restrict__ out)
{
  __shared__ __align__(16) float xs[FFTC];   // current x (identical in all CTAs)
  __shared__ __align__(16) float hs[16];     // this CTA's h rows
  __shared__ __align__(16) float lg[FFTC];   // logits (all CTAs)
  __shared__ int s_sel;
  const int tid = threadIdx.x;
  const int blk = blockIdx.x;
  const int w = tid >> 5, lane = tid & 31;
  const int r = blk*16 + w;                  // h row owned by this warp
  const int zrow = tid >> 1;
  const int half = tid & 1;
  const int in0 = blk*16 + half*8;           // inner-dim base for partial z
  float* ring = g_ring + (size_t)blk*MEMCOLS*FFTC;

  if (tid < FFTC) xs[tid] = g_emb[127*FFTC + tid];
  __syncthreads();

  for (int t=0; t<TT; ++t){
    const int f = t >> 7;
    const int base = t*SPS;

    #pragma unroll 1
    for (int j=0; j<NL; ++j){
      const int col = ((1<<j) - 1) + (t & ((1<<j) - 1));
      // ---- prefetch everything independent of this layer's input x ----
      F8 wp = ldnc8(WVp + (size_t)(j*FFTC + r)*FFTC + lane*8);
      float mc[8];
      *(float4*)(mc)   = *(const float4*)(ring + col*FFTC + lane*8);
      *(float4*)(mc+4) = *(const float4*)(ring + col*FFTC + lane*8 + 4);
      F8 wc = ldnc8(WVc + (size_t)(j*FFTC + r)*FFTC + lane*8);
      F8 wo = ldnc8(Wow + (size_t)(j*FFTC + zrow)*FFTC + in0);
      float part = (lane==0) ? g_cond[(j*16 + f)*FFTC + r] : 0.0f;
      part = dot8(wp, mc, part);                // past-tap dot: before the wait

      if (j > 0){
        float wobp = (tid<FFTC) ? Wob[(j-1)*FFTC + tid] : 0.0f;
        if (tid==0) poll_flag(base + (j-1), NCTA);   // single poller
        __syncthreads();                              // wakes all warps together
        if (tid < FFTC){
          float s1 = wobp;
          const float* gp = g_part + (j-1)*NCTA*FFTC + tid;
          #pragma unroll
          for (int k=0;k<NCTA;k++) s1 += ldcg(gp + k*FFTC);
          xs[tid] = fmaxf(s1 + xs[tid], 0.0f);        // x' = relu(z + b + x)
        }
        __syncthreads();
      }
      part = dot8(wc, xs + lane*8, part);
      part = red32(part);
      if (lane==0) hs[w] = fmaxf(part, 0.0f);
      __syncthreads();
      // partial z over this CTA's 16 h rows
      float pk = dot8(wo, hs + half*8, 0.0f);
      float oth = __shfl_xor_sync(0xffffffffu, pk, 1);
      float z = (half==0) ? (pk + oth) : (oth + pk);
      if (half==0) g_part[(j*NCTA + blk)*FFTC + zrow] = z;
      __syncthreads();                                // partial stores before release
      if (tid==0) release_flag(base + j);
      if (tid < FFTC) ring[col*FFTC + tid] = xs[tid]; // private, outside release drain
    }

    { // ---- logits: x' after layer 10, then partial endw slice ----
      F8 ew = ldnc8(endw + (size_t)zrow*FFTC + in0);
      float wobL = (tid<FFTC) ? Wob[10*FFTC + tid] : 0.0f;
      if (tid==0) poll_flag(base + 10, NCTA);
      __syncthreads();
      if (tid < FFTC){
        float s1 = wobL;
        const float* gp = g_part + 10*NCTA*FFTC + tid;
        #pragma unroll
        for (int k=0;k<NCTA;k++) s1 += ldcg(gp + k*FFTC);
        xs[tid] = fmaxf(s1 + xs[tid], 0.0f);
      }
      __syncthreads();
      float pk = dot8(ew, xs + in0, 0.0f);
      float oth = __shfl_xor_sync(0xffffffffu, pk, 1);
      float z = (half==0) ? (pk + oth) : (oth + pk);
      if (half==0) g_part[(11*NCTA + blk)*FFTC + zrow] = z;
      __syncthreads();
      if (tid==0) release_flag(base + 11);
    }

    { // ---- sampler: ALL CTAs redundantly (deterministic); no broadcast sync ----
      float u = (tid < 32) ? samples[t] : 0.0f;       // prefetch before the wait
      if (tid==0) poll_flag(base + 11, NCTA);
      __syncthreads();
      if (tid < FFTC){
        float s1 = endb[tid];
        const float* gp = g_part + 11*NCTA*FFTC + tid;
        #pragma unroll
        for (int k=0;k<NCTA;k++) s1 += ldcg(gp + k*FFTC);
        lg[tid] = s1;                                 // C_SCALE == 1
      }
      __syncthreads();
      if (tid < 32){
        float4 va = *(const float4*)(lg + lane*8);
        float4 vb = *(const float4*)(lg + lane*8 + 4);
        float v[8] = {va.x,va.y,va.z,va.w,vb.x,vb.y,vb.z,vb.w};
        float m = v[0];
        #pragma unroll
        for (int k=1;k<8;k++) m = fmaxf(m, v[k]);
        #pragma unroll
        for (int k=16;k>0;k>>=1) m = fmaxf(m, __shfl_xor_sync(0xffffffffu, m, k));
        float e[8]; float sl = 0.0f;
        #pragma unroll
        for (int k=0;k<8;k++){ e[k] = expf(v[k] - m); sl += e[k]; }
        float tot = sl;
        #pragma unroll
        for (int k=16;k>0;k>>=1) tot += __shfl_xor_sync(0xffffffffu, tot, k);
        float cs[8]; float c = 0.0f;
        #pragma unroll
        for (int k=0;k<8;k++){ c += e[k] / tot; cs[k] = c; }
        float inc = c;
        #pragma unroll
        for (int k=1;k<32;k<<=1){ float o = __shfl_up_sync(0xffffffffu, inc, k); if (lane>=k) inc += o; }
        float off = __shfl_up_sync(0xffffffffu, inc, 1);
        if (lane == 0) off = 0.0f;
        int cand = 1<<30;
        #pragma unroll
        for (int k=0;k<8;k++) if (cand == (1<<30) && (off + cs[k]) > u) cand = lane*8 + k;
        #pragma unroll
        for (int k=16;k>0;k>>=1) cand = min(cand, __shfl_xor_sync(0xffffffffu, cand, k));
        int sel = (cand >= 256) ? 0 : cand;
        if (lane == 0){
          s_sel = sel;
          if (blk == 0) out[t] = (float)sel;
        }
      }
      __syncthreads();
      if (tid < FFTC) xs[tid] = g_emb[s_sel*FFTC + tid];  // next step's x0, locally
      __syncthreads();
    }
  }
}

extern "C" void kernel_launch(void* const* d_in, const int* in_sizes, int n_in,
                              void* d_out, int out_size) {
  // ---- Robust input binding: identify tensors by element count, not position.
  int i1280=-1, i2048=-1, i225280=-1, i2816=-1, i256=-1;
  int i65536[2] = {-1,-1}; int n65536 = 0;
  int i720[3] = {-1,-1,-1}; int n720 = 0;
  for (int i=0;i<n_in;i++){
    switch (in_sizes[i]){
      case 1280:   i1280 = i; break;
      case 2048:   i2048 = i; break;
      case 225280: i225280 = i; break;
      case 2816:   i2816 = i; break;
      case 256:    i256 = i; break;
      case 65536:  if (n65536 < 2) i65536[n65536++] = i; break;
      case 720896: if (n720 < 3) i720[n720++] = i; break;
      default: break;
    }
  }
  if (i1280<0 || i2048<0 || i225280<0 || i2816<0 || i256<0 || n65536!=2 || n720!=3){
    i1280=0; i2048=1; i65536[0]=2; i225280=3; i720[0]=4; i720[1]=5; i720[2]=6;
    i2816=7; i65536[1]=8; i256=9;
  }
  const float* y        = (const float*)d_in[i1280];     // [80,16]
  const float* samples  = (const float*)d_in[i2048];     // [2048]
  const float* condW    = (const float*)d_in[i225280];   // [2816,80]
  const float* Wob      = (const float*)d_in[i2816];     // [11,256]
  const float* endb     = (const float*)d_in[i256];      // [256]
  const float* emb_raw  = (const float*)d_in[i65536[0]]; // [256,256]
  const float* endw     = (const float*)d_in[i65536[1]]; // [256,256]
  int before = 0;
  for (int k=0;k<3;k++) if (i720[k] < i2816) before++;
  const float *WVp, *WVc, *Wow;
  if (before == 0) { Wow = (const float*)d_in[i720[0]];
                     WVp = (const float*)d_in[i720[1]];
                     WVc = (const float*)d_in[i720[2]]; }
  else             { WVp = (const float*)d_in[i720[0]];
                     WVc = (const float*)d_in[i720[1]];
                     Wow = (const float*)d_in[i720[2]]; }
  float* out = (float*)d_out;                            // [2048] sampled ids (as float32)

  init_all<<<2048,256>>>(y, emb_raw, condW);
  fftnet_main<<<NCTA,512>>>(WVp, WVc, Wow, Wob, endw, endb, samples, out);
}

// round 12
// speedup vs baseline: 3.1313x; 1.0526x over previous
#include <cuda_runtime.h>
#include <cstdint>

#define FFTC 256
#define NL 11
#define TT 2048
#define NCTA 16
#define SPS 12                       // flags/step: s=0..10 layer-partial publishes; s=11 logits partials
#define NFLAGS (TT*SPS)
#define FSTRIDE 32                   // one 128B L2 line per flag
#define MEMCOLS 2047                 // sum of dilations 1+2+...+1024

// Persistent state (recomputed every kernel_launch for determinism)
__device__ float g_ring[(size_t)NCTA*MEMCOLS*FFTC]; // PRIVATE ring buffer per CTA
__device__ float g_cond[NL*16*FFTC];                // cond projections per (layer, frame)
__device__ float g_emb[256*FFTC];                   // tanh(emb_raw)
__device__ float g_part[12*NCTA*FFTC];              // per-layer (+logits) partial z vectors
__device__ unsigned g_flags[(size_t)NFLAGS*FSTRIDE];

__device__ __forceinline__ void poll_flag(int s, unsigned expect){
  const unsigned* p = g_flags + (size_t)s*FSTRIDE;
  unsigned v;
  do {
    asm volatile("ld.acquire.gpu.global.u32 %0, [%1];" : "=r"(v) : "l"(p) : "memory");
  } while (v < expect);
}
__device__ __forceinline__ void release_flag(int s){
  asm volatile("red.release.gpu.global.add.u32 [%0], %1;"
               :: "l"(g_flags + (size_t)s*FSTRIDE), "r"(1u) : "memory");
}

// 8-float (32B) weight load: read-only, keep resident in L2 (evict_last).
struct F8 { float f[8]; };
__device__ __forceinline__ F8 ldnc8(const float* p){
  unsigned long long a,b,c,d;
  asm volatile("ld.global.nc.L2::evict_last.v4.b64 {%0,%1,%2,%3}, [%4];"
               : "=l"(a), "=l"(b), "=l"(c), "=l"(d) : "l"(p));
  F8 r;
  r.f[0] = __uint_as_float((unsigned)(a));        r.f[1] = __uint_as_float((unsigned)(a>>32));
  r.f[2] = __uint_as_float((unsigned)(b));        r.f[3] = __uint_as_float((unsigned)(b>>32));
  r.f[4] = __uint_as_float((unsigned)(c));        r.f[5] = __uint_as_float((unsigned)(c>>32));
  r.f[6] = __uint_as_float((unsigned)(d));        r.f[7] = __uint_as_float((unsigned)(d>>32));
  return r;
}
// cross-CTA data: bypass L1 (L2 is the coherence point for gpu-scope flags)
__device__ __forceinline__ float ldcg(const float* p){
  float v;
  asm volatile("ld.global.cg.f32 %0, [%1];" : "=f"(v) : "l"(p));
  return v;
}

__device__ __forceinline__ float dot8(const F8& w, const float* v, float p){
  #pragma unroll
  for (int k=0;k<8;k++) p = fmaf(w.f[k], v[k], p);
  return p;
}
__device__ __forceinline__ float red32(float p){
  #pragma unroll
  for (int k=16;k>0;k>>=1) p += __shfl_xor_sync(0xffffffffu, p, k);
  return p;
}

// ---------------- init + precompute fused ----------------
__global__ void init_all(const float* __restrict__ y,
                         const float* __restrict__ emb_raw,
                         const float* __restrict__ condW){
  const int b = blockIdx.x, tid = threadIdx.x;
  if (b < 256) {
    g_emb[b*256 + tid] = tanhf(emb_raw[b*256 + tid]);
  } else if (b < 256 + NL*16) {
    int b2 = b - 256;
    int j = b2 >> 4, f = b2 & 15;
    int row = j*256 + tid;
    float acc = 0.0f;
    #pragma unroll
    for (int c=0; c<80; c++) acc = fmaf(condW[row*80 + c], y[c*16 + f], acc);
    g_cond[(j*16 + f)*256 + tid] = acc;
  }
  size_t i = (size_t)b*blockDim.x + tid;
  size_t stride = (size_t)gridDim.x*blockDim.x;
  for (size_t k=i; k<(size_t)NCTA*MEMCOLS*FFTC; k+=stride) g_ring[k] = 0.0f;
  for (size_t k=i; k<(size_t)NFLAGS*FSTRIDE; k+=stride) g_flags[k] = 0u;
}

// ---------------- main persistent kernel: 16 CTAs x 512 threads ----------------
// Stage A: warp-per-h-row (16 warps = 16 rows/CTA), 8 floats/lane, full-warp reduce.
// Partial z: zrow = tid>>1 (256 outputs), half = tid&1; 16-wide inner slice per CTA.
// One chip-wide sync per layer; x', logits and SAMPLER computed redundantly per CTA.
// KEY SCHEDULING RULE: all global loads are ISSUED before the flag wait and
// CONSUMED only after it, so DRAM/L2 latency hides under the wait.
__global__ void __launch_bounds__(512,1) fftnet_main(
  const float* __restrict__ WVp, const float* __restrict__ WVc,
  const float* __restrict__ Wow, const float* __restrict__ Wob,
  const float* __restrict__ endw, const float* __restrict__ endb,
  const float* __restrict__ samples, float* __restrict__ out)
{
  __shared__ __align__(16) float xs[FFTC];   // current x (identical in all CTAs)
  __shared__ __align__(16) float hs[16];     // this CTA's h rows
  __shared__ __align__(16) float lg[FFTC];   // logits (all CTAs)
  __shared__ __align__(16) float es[FFTC];   // staged emb row (sampler)
  __shared__ int s_sel;
  const int tid = threadIdx.x;
  const int blk = blockIdx.x;
  const int w = tid >> 5, lane = tid & 31;
  const int r = blk*16 + w;                  // h row owned by this warp
  const int zrow = tid >> 1;
  const int half = tid & 1;
  const int in0 = blk*16 + half*8;           // inner-dim base for partial z
  float* ring = g_ring + (size_t)blk*MEMCOLS*FFTC;

  if (tid < FFTC) xs[tid] = g_emb[127*FFTC + tid];
  __syncthreads();

  for (int t=0; t<TT; ++t){
    const int f = t >> 7;
    const int base = t*SPS;

    #pragma unroll 1
    for (int j=0; j<NL; ++j){
      const int col = ((1<<j) - 1) + (t & ((1<<j) - 1));
      // ---- ISSUE loads only; consume nothing until after the wait ----
      F8 wp = ldnc8(WVp + (size_t)(j*FFTC + r)*FFTC + lane*8);
      float mc[8];
      *(float4*)(mc)   = *(const float4*)(ring + col*FFTC + lane*8);
      *(float4*)(mc+4) = *(const float4*)(ring + col*FFTC + lane*8 + 4);
      F8 wc = ldnc8(WVc + (size_t)(j*FFTC + r)*FFTC + lane*8);
      F8 wo = ldnc8(Wow + (size_t)(j*FFTC + zrow)*FFTC + in0);
      float cnd = (lane==0) ? g_cond[(j*16 + f)*FFTC + r] : 0.0f;
      float wobp = (j>0 && tid<FFTC) ? Wob[(j-1)*FFTC + tid] : 0.0f;

      if (j > 0){
        if (tid==0) poll_flag(base + (j-1), NCTA);   // single poller
        __syncthreads();                              // wakes all warps together
        if (tid < FFTC){
          float s1 = wobp;
          const float* gp = g_part + (j-1)*NCTA*FFTC + tid;
          #pragma unroll
          for (int k=0;k<NCTA;k++) s1 += ldcg(gp + k*FFTC);
          xs[tid] = fmaxf(s1 + xs[tid], 0.0f);        // x' = relu(z + b + x)
        }
        __syncthreads();
      }
      // ---- all math after the wait (loads have had the wait to land) ----
      float part = cnd;
      part = dot8(wp, mc, part);                      // same FP order as before
      part = dot8(wc, xs + lane*8, part);
      part = red32(part);
      if (lane==0) hs[w] = fmaxf(part, 0.0f);
      __syncthreads();
      // partial z over this CTA's 16 h rows
      float pk = dot8(wo, hs + half*8, 0.0f);
      float oth = __shfl_xor_sync(0xffffffffu, pk, 1);
      float z = (half==0) ? (pk + oth) : (oth + pk);
      if (half==0) g_part[(j*NCTA + blk)*FFTC + zrow] = z;
      __syncthreads();                                // partial stores before release
      if (tid==0) release_flag(base + j);
      if (tid < FFTC) ring[col*FFTC + tid] = xs[tid]; // private, outside release drain
    }

    { // ---- logits: x' after layer 10, then partial endw slice ----
      F8 ew = ldnc8(endw + (size_t)zrow*FFTC + in0);
      float wobL = (tid<FFTC) ? Wob[10*FFTC + tid] : 0.0f;
      if (tid==0) poll_flag(base + 10, NCTA);
      __syncthreads();
      if (tid < FFTC){
        float s1 = wobL;
        const float* gp = g_part + 10*NCTA*FFTC + tid;
        #pragma unroll
        for (int k=0;k<NCTA;k++) s1 += ldcg(gp + k*FFTC);
        xs[tid] = fmaxf(s1 + xs[tid], 0.0f);
      }
      __syncthreads();
      float pk = dot8(ew, xs + in0, 0.0f);
      float oth = __shfl_xor_sync(0xffffffffu, pk, 1);
      float z = (half==0) ? (pk + oth) : (oth + pk);
      if (half==0) g_part[(11*NCTA + blk)*FFTC + zrow] = z;
      __syncthreads();
      if (tid==0) release_flag(base + 11);
    }

    { // ---- sampler: ALL CTAs redundantly (deterministic); no broadcast sync ----
      float u = (tid < 32) ? samples[t] : 0.0f;       // prefetch before the wait
      if (tid==0) poll_flag(base + 11, NCTA);
      __syncthreads();
      if (tid < FFTC){
        float s1 = endb[tid];
        const float* gp = g_part + 11*NCTA*FFTC + tid;
        #pragma unroll
        for (int k=0;k<NCTA;k++) s1 += ldcg(gp + k*FFTC);
        lg[tid] = s1;                                 // C_SCALE == 1
      }
      __syncthreads();
      if (tid < 32){
        float4 va = *(const float4*)(lg + lane*8);
        float4 vb = *(const float4*)(lg + lane*8 + 4);
        float v[8] = {va.x,va.y,va.z,va.w,vb.x,vb.y,vb.z,vb.w};
        float m = v[0];
        #pragma unroll
        for (int k=1;k<8;k++) m = fmaxf(m, v[k]);
        #pragma unroll
        for (int k=16;k>0;k>>=1) m = fmaxf(m, __shfl_xor_sync(0xffffffffu, m, k));
        float e[8]; float sl = 0.0f;
        #pragma unroll
        for (int k=0;k<8;k++){ e[k] = expf(v[k] - m); sl += e[k]; }
        float tot = sl;
        #pragma unroll
        for (int k=16;k>0;k>>=1) tot += __shfl_xor_sync(0xffffffffu, tot, k);
        float cs[8]; float c = 0.0f;
        #pragma unroll
        for (int k=0;k<8;k++){ c += e[k] / tot; cs[k] = c; }
        float inc = c;
        #pragma unroll
        for (int k=1;k<32;k<<=1){ float o = __shfl_up_sync(0xffffffffu, inc, k); if (lane>=k) inc += o; }
        float off = __shfl_up_sync(0xffffffffu, inc, 1);
        if (lane == 0) off = 0.0f;
        int cand = 1<<30;
        #pragma unroll
        for (int k=0;k<8;k++) if (cand == (1<<30) && (off + cs[k]) > u) cand = lane*8 + k;
        #pragma unroll
        for (int k=16;k>0;k>>=1) cand = min(cand, __shfl_xor_sync(0xffffffffu, cand, k));
        int sel = (cand >= 256) ? 0 : cand;
        if (lane == 0){
          s_sel = sel;
          if (blk == 0) out[t] = (float)sel;
        }
        // stage emb[sel] via wide evict_last loads (L2-resident emb)
        F8 er = ldnc8(g_emb + sel*FFTC + lane*8);
        #pragma unroll
        for (int k=0;k<8;k++) es[lane*8 + k] = er.f[k];
      }
      __syncthreads();
      if (tid < FFTC) xs[tid] = es[tid];              // next step's x0, locally
      __syncthreads();
    }
  }
}

extern "C" void kernel_launch(void* const* d_in, const int* in_sizes, int n_in,
                              void* d_out, int out_size) {
  // ---- Robust input binding: identify tensors by element count, not position.
  int i1280=-1, i2048=-1, i225280=-1, i2816=-1, i256=-1;
  int i65536[2] = {-1,-1}; int n65536 = 0;
  int i720[3] = {-1,-1,-1}; int n720 = 0;
  for (int i=0;i<n_in;i++){
    switch (in_sizes[i]){
      case 1280:   i1280 = i; break;
      case 2048:   i2048 = i; break;
      case 225280: i225280 = i; break;
      case 2816:   i2816 = i; break;
      case 256:    i256 = i; break;
      case 65536:  if (n65536 < 2) i65536[n65536++] = i; break;
      case 720896: if (n720 < 3) i720[n720++] = i; break;
      default: break;
    }
  }
  if (i1280<0 || i2048<0 || i225280<0 || i2816<0 || i256<0 || n65536!=2 || n720!=3){
    i1280=0; i2048=1; i65536[0]=2; i225280=3; i720[0]=4; i720[1]=5; i720[2]=6;
    i2816=7; i65536[1]=8; i256=9;
  }
  const float* y        = (const float*)d_in[i1280];     // [80,16]
  const float* samples  = (const float*)d_in[i2048];     // [2048]
  const float* condW    = (const float*)d_in[i225280];   // [2816,80]
  const float* Wob      = (const float*)d_in[i2816];     // [11,256]
  const float* endb     = (const float*)d_in[i256];      // [256]
  const float* emb_raw  = (const float*)d_in[i65536[0]]; // [256,256]
  const float* endw     = (const float*)d_in[i65536[1]]; // [256,256]
  int before = 0;
  for (int k=0;k<3;k++) if (i720[k] < i2816) before++;
  const float *WVp, *WVc, *Wow;
  if (before == 0) { Wow = (const float*)d_in[i720[0]];
                     WVp = (const float*)d_in[i720[1]];
                     WVc = (const float*)d_in[i720[2]]; }
  else             { WVp = (const float*)d_in[i720[0]];
                     WVc = (const float*)d_in[i720[1]];
                     Wow = (const float*)d_in[i720[2]]; }
  float* out = (float*)d_out;                            // [2048] sampled ids (as float32)

  init_all<<<2048,256>>>(y, emb_raw, condW);
  fftnet_main<<<NCTA,512>>>(WVp, WVc, Wow, Wob, endw, endb, samples, out);
}